// round 2
// baseline (speedup 1.0000x reference)
#include <cuda_runtime.h>
#include <math.h>

#define B_  64
#define T_  512
#define D_  512
#define H_  1024
#define G4  4096
#define M1  32768          // B_*T_
#define NBLK 128
#define RTHREADS 128
#define SMEM_BYTES ((32768 + 2048) * 4)   // Bs[1024][32] + As[32][64]

// ---------------------------------------------------------------------------
// Device globals (allocation-free scratch)
// ---------------------------------------------------------------------------
__device__ float g_xg[(size_t)M1 * G4];    // xg = x@Wx + b   (512 MB)
__device__ float g_hb[2][B_ * H_];         // double-buffered hidden state
__device__ unsigned g_cnt;                 // grid barrier counter
__device__ unsigned g_gen;                 // grid barrier generation

// ---------------------------------------------------------------------------
// f32x2 packed-FMA helpers (Blackwell 2xFP32 path; only reachable via PTX)
// ---------------------------------------------------------------------------
__device__ __forceinline__ unsigned long long pack2(float x, float y) {
    unsigned long long r;
    asm("mov.b64 %0, {%1, %2};" : "=l"(r) : "f"(x), "f"(y));
    return r;
}
__device__ __forceinline__ void fma2(unsigned long long& d,
                                     unsigned long long a,
                                     unsigned long long b) {
    asm("fma.rn.f32x2 %0, %1, %2, %0;" : "+l"(d) : "l"(a), "l"(b));
}
__device__ __forceinline__ float2 unpack2(unsigned long long v) {
    float lo, hi;
    asm("mov.b64 {%0, %1}, %2;" : "=f"(lo), "=f"(hi) : "l"(v));
    return make_float2(lo, hi);
}

// ---------------------------------------------------------------------------
// Phase 1: xg[M1, G4] = x[M1, D] @ Wx[D, G4] + bias
// 128x128 tile, BK=8, 256 threads, 8x8 microtile, f32x2 packed FMA
// ---------------------------------------------------------------------------
__global__ __launch_bounds__(256) void gemm_xw(const float* __restrict__ x,
                                               const float* __restrict__ Wx,
                                               const float* __restrict__ bias) {
    __shared__ float As[8][128];
    __shared__ float Bs[8][128];

    const int bm = blockIdx.y;
    const int bn = blockIdx.x;
    const int tid = threadIdx.x;
    const int tx = tid & 15;        // col group (8 cols)
    const int ty = tid >> 4;        // row group (8 rows)

    unsigned long long acc2[4][8];  // row-pairs x 8 cols
#pragma unroll
    for (int p = 0; p < 4; ++p)
#pragma unroll
        for (int j = 0; j < 8; ++j) acc2[p][j] = 0ull;

    const int a_lrow = tid >> 1;
    const int a_kc   = (tid & 1) * 4;
    const float* Aptr = x + (size_t)(bm * 128 + a_lrow) * D_;

    const int b_lrow = tid >> 5;
    const int b_lcol = (tid & 31) * 4;
    const int ncol0 = bn * 128;

    for (int k0 = 0; k0 < D_; k0 += 8) {
        float4 av = *(const float4*)(Aptr + k0 + a_kc);
        float4 bv = *(const float4*)(Wx + (size_t)(k0 + b_lrow) * G4 + ncol0 + b_lcol);

        As[a_kc + 0][a_lrow] = av.x;
        As[a_kc + 1][a_lrow] = av.y;
        As[a_kc + 2][a_lrow] = av.z;
        As[a_kc + 3][a_lrow] = av.w;
        *(float4*)&Bs[b_lrow][b_lcol] = bv;
        __syncthreads();

#pragma unroll
        for (int k = 0; k < 8; ++k) {
            float4 a0 = *(const float4*)&As[k][ty * 8];
            float4 a1 = *(const float4*)&As[k][ty * 8 + 4];
            float4 b0 = *(const float4*)&Bs[k][tx * 8];
            float4 b1 = *(const float4*)&Bs[k][tx * 8 + 4];
            unsigned long long a2[4];
            a2[0] = pack2(a0.x, a0.y);
            a2[1] = pack2(a0.z, a0.w);
            a2[2] = pack2(a1.x, a1.y);
            a2[3] = pack2(a1.z, a1.w);
            unsigned long long bd[8];
            bd[0] = pack2(b0.x, b0.x); bd[1] = pack2(b0.y, b0.y);
            bd[2] = pack2(b0.z, b0.z); bd[3] = pack2(b0.w, b0.w);
            bd[4] = pack2(b1.x, b1.x); bd[5] = pack2(b1.y, b1.y);
            bd[6] = pack2(b1.z, b1.z); bd[7] = pack2(b1.w, b1.w);
#pragma unroll
            for (int p = 0; p < 4; ++p)
#pragma unroll
                for (int j = 0; j < 8; ++j) fma2(acc2[p][j], a2[p], bd[j]);
        }
        __syncthreads();
    }

    float bb[8];
#pragma unroll
    for (int j = 0; j < 8; ++j) bb[j] = bias[ncol0 + tx * 8 + j];

#pragma unroll
    for (int p = 0; p < 4; ++p) {
        float rlo[8], rhi[8];
#pragma unroll
        for (int j = 0; j < 8; ++j) {
            float2 v = unpack2(acc2[p][j]);
            rlo[j] = v.x + bb[j];
            rhi[j] = v.y + bb[j];
        }
        size_t row0 = (size_t)(bm * 128 + ty * 8 + 2 * p);
        float* c0 = g_xg + row0 * G4 + ncol0 + tx * 8;
        float* c1 = c0 + G4;
        *(float4*)(c0)     = make_float4(rlo[0], rlo[1], rlo[2], rlo[3]);
        *(float4*)(c0 + 4) = make_float4(rlo[4], rlo[5], rlo[6], rlo[7]);
        *(float4*)(c1)     = make_float4(rhi[0], rhi[1], rhi[2], rhi[3]);
        *(float4*)(c1 + 4) = make_float4(rhi[4], rhi[5], rhi[6], rhi[7]);
    }
}

// ---------------------------------------------------------------------------
// Init: zero h buffer 0 and barrier counter (every launch -> replay-safe)
// ---------------------------------------------------------------------------
__global__ void init_state() {
    int idx = blockIdx.x * blockDim.x + threadIdx.x;   // 65536 threads
    g_hb[0][idx] = 0.0f;
    if (idx == 0) g_cnt = 0u;
}

// ---------------------------------------------------------------------------
// Grid-wide barrier (all NBLK blocks resident by construction)
// ---------------------------------------------------------------------------
__device__ __forceinline__ void grid_barrier() {
    __threadfence();
    __syncthreads();
    if (threadIdx.x == 0) {
        volatile unsigned* vg = &g_gen;
        unsigned gen = *vg;
        if (atomicAdd(&g_cnt, 1u) == NBLK - 1) {
            atomicExch(&g_cnt, 0u);
            __threadfence();
            atomicAdd((unsigned*)&g_gen, 1u);
        } else {
            while (*vg == gen) { }
        }
    }
    __syncthreads();
}

// ---------------------------------------------------------------------------
// Persistent recurrence kernel.
// Block bx owns hidden columns j0..j0+7 (j0 = bx*8) across ALL 4 gates.
// Bs[k][c]: c = jj*4 + g  (gate-interleaved) -> thread tx holds all 4 gates
// for hidden col j0+tx. Wh slice resident in smem for all 512 steps.
// GEMM: 64 rows x 32 cols x K=1024, 128 threads, 4x4 microtile, f32x2.
// ---------------------------------------------------------------------------
__global__ void __launch_bounds__(RTHREADS, 1)
lstm_persist(const float* __restrict__ Wh, float* __restrict__ out) {
    extern __shared__ float smem[];
    float* Bs = smem;             // [1024][32]
    float* As = smem + 32768;     // [32][64] swizzled

    const int tid = threadIdx.x;
    const int j0 = blockIdx.x * 8;
    const int ty = tid >> 3;      // 0..15 (4 rows each)
    const int tx = tid & 7;       // 0..7  (hidden col j0+tx)

    // One-time Wh slice load (gate-interleaved columns)
    for (int idx = tid; idx < 32768; idx += RTHREADS) {
        int k = idx >> 5, c = idx & 31;
        Bs[idx] = Wh[(size_t)k * G4 + (c & 3) * H_ + j0 + (c >> 2)];
    }

    // Per-thread A-fill coordinates (4 float4 tasks per 32-k chunk)
    int frow[4], fk4[4], fs[4];
#pragma unroll
    for (int it = 0; it < 4; ++it) {
        int t4 = tid + it * RTHREADS;
        frow[it] = t4 >> 3;            // 0..63
        fk4[it]  = (t4 & 7) * 4;       // 0..28
        fs[it]   = (t4 & 7) << 2;      // swizzle = ((k>>2)&7)<<2
    }

    float cc[4] = {0.f, 0.f, 0.f, 0.f};   // cell state in registers
    __syncthreads();

    for (int t = 0; t < T_; ++t) {
        const float* hin = g_hb[t & 1];
        unsigned long long acc2[2][4];
#pragma unroll
        for (int p = 0; p < 2; ++p)
#pragma unroll
            for (int g = 0; g < 4; ++g) acc2[p][g] = 0ull;

        float4 pf[4];
#pragma unroll
        for (int it = 0; it < 4; ++it)
            pf[it] = __ldcg((const float4*)(hin + frow[it] * H_ + fk4[it]));

        for (int kc = 0; kc < 32; ++kc) {
            // stage prefetched chunk into swizzled As
#pragma unroll
            for (int it = 0; it < 4; ++it) {
                int rp = frow[it] ^ fs[it];
                As[(fk4[it] + 0) * 64 + rp] = pf[it].x;
                As[(fk4[it] + 1) * 64 + rp] = pf[it].y;
                As[(fk4[it] + 2) * 64 + rp] = pf[it].z;
                As[(fk4[it] + 3) * 64 + rp] = pf[it].w;
            }
            __syncthreads();
            if (kc < 31) {
                int kb = (kc + 1) * 32;
#pragma unroll
                for (int it = 0; it < 4; ++it)
                    pf[it] = __ldcg((const float4*)(hin + frow[it] * H_ + kb + fk4[it]));
            }
            const float* bsp = Bs + kc * 1024;
#pragma unroll
            for (int ku = 0; ku < 32; ku += 4) {
                const float* ap = As + ((ty * 4) ^ (((ku >> 2) & 7) << 2));
#pragma unroll
                for (int v = 0; v < 4; ++v) {
                    int k = ku + v;
                    float4 av = *(const float4*)(ap + k * 64);
                    float4 bv = *(const float4*)(bsp + k * 32 + tx * 4);
                    unsigned long long a20 = pack2(av.x, av.y);
                    unsigned long long a21 = pack2(av.z, av.w);
                    unsigned long long bd0 = pack2(bv.x, bv.x);
                    unsigned long long bd1 = pack2(bv.y, bv.y);
                    unsigned long long bd2 = pack2(bv.z, bv.z);
                    unsigned long long bd3 = pack2(bv.w, bv.w);
                    fma2(acc2[0][0], a20, bd0);
                    fma2(acc2[0][1], a20, bd1);
                    fma2(acc2[0][2], a20, bd2);
                    fma2(acc2[0][3], a20, bd3);
                    fma2(acc2[1][0], a21, bd0);
                    fma2(acc2[1][1], a21, bd1);
                    fma2(acc2[1][2], a21, bd2);
                    fma2(acc2[1][3], a21, bd3);
                }
            }
            __syncthreads();
        }

        // Pointwise LSTM cell (fully thread-local; c in registers)
        float* hout = g_hb[(t + 1) & 1];
#pragma unroll
        for (int p = 0; p < 2; ++p) {
            float2 gi = unpack2(acc2[p][0]);
            float2 gf = unpack2(acc2[p][1]);
            float2 gg = unpack2(acc2[p][2]);
            float2 go = unpack2(acc2[p][3]);
#pragma unroll
            for (int q = 0; q < 2; ++q) {
                int i = p * 2 + q;
                int b = ty * 4 + i;
                const float* xg = g_xg + ((size_t)b * T_ + t) * G4 + j0 + tx;
                float vi = (q ? gi.y : gi.x) + xg[0];
                float vf = (q ? gf.y : gf.x) + xg[H_];
                float vg = (q ? gg.y : gg.x) + xg[2 * H_];
                float vo = (q ? go.y : go.x) + xg[3 * H_];
                float si = 1.0f / (1.0f + expf(-vi));
                float sf = 1.0f / (1.0f + expf(-vf));
                float tg = tanhf(vg);
                float so = 1.0f / (1.0f + expf(-vo));
                float c = sf * cc[i] + si * tg;
                cc[i] = c;
                float h = so * tanhf(c);
                hout[b * H_ + j0 + tx] = h;
                out[((size_t)b * T_ + t) * H_ + j0 + tx] = h;
            }
        }

        if (t < T_ - 1) grid_barrier();
    }
}

// ---------------------------------------------------------------------------
// Launch: exactly 3 graph nodes
// ---------------------------------------------------------------------------
extern "C" void kernel_launch(void* const* d_in, const int* in_sizes, int n_in,
                              void* d_out, int out_size) {
    const float* x    = (const float*)d_in[0];   // [B, T, D]
    const float* Wx   = (const float*)d_in[1];   // [D, 4H]
    const float* Wh   = (const float*)d_in[2];   // [H, 4H]
    const float* bias = (const float*)d_in[3];   // [4H]
    float* out = (float*)d_out;                  // [B, T, H]

    cudaFuncSetAttribute(lstm_persist,
                         cudaFuncAttributeMaxDynamicSharedMemorySize, SMEM_BYTES);

    dim3 g1(G4 / 128, M1 / 128);                 // (32, 256)
    gemm_xw<<<g1, 256>>>(x, Wx, bias);
    init_state<<<256, 256>>>();
    lstm_persist<<<NBLK, RTHREADS, SMEM_BYTES>>>(Wh, out);
}